// round 10
// baseline (speedup 1.0000x reference)
#include <cuda_runtime.h>
#include <cuda_bf16.h>
#include <cstdint>

#define NN 50000
#define CC 128
#define EE 640000
#define KK 40
#define LN_EPS 1e-5f
#define SCAN_BS 1024
#define MAX_NB 64

// Scratch
__device__ int   g_cnt[NN];
__device__ int   g_rowstart[NN + 1];
__device__ int   g_cursor[NN];
__device__ int   g_tmp[NN];
__device__ int   g_bsum[MAX_NB];
__device__ float g_dinv[NN];
__device__ float g_h[(size_t)NN * CC];
__device__ int2  g_edge[EE];   // (src, norm bits) packed

__device__ __forceinline__ uint32_t f2tf32(float f) {
    uint32_t r;
    asm("cvt.rna.tf32.f32 %0, %1;" : "=r"(r) : "f"(f));
    return r;
}

// ---------------------------------------------------------------- degree ----
__global__ void k_count(const int* __restrict__ dst, int e) {
    int i = blockIdx.x * blockDim.x + threadIdx.x;
    if (i < e) atomicAdd(&g_cnt[dst[i]], 1);
}

// ------------------------------------------------------------------ scan ----
__global__ void k_scan1(int n) {
    __shared__ int sm[SCAN_BS];
    int i = blockIdx.x * SCAN_BS + threadIdx.x;
    int v = (i < n) ? g_cnt[i] : 0;
    sm[threadIdx.x] = v;
    __syncthreads();
#pragma unroll
    for (int off = 1; off < SCAN_BS; off <<= 1) {
        int t = (threadIdx.x >= off) ? sm[threadIdx.x - off] : 0;
        __syncthreads();
        sm[threadIdx.x] += t;
        __syncthreads();
    }
    if (i < n) g_tmp[i] = sm[threadIdx.x];
    if (threadIdx.x == SCAN_BS - 1) g_bsum[blockIdx.x] = sm[SCAN_BS - 1];
}

// scan of block sums fused with final CSR offset/dinv computation
__global__ void k_scan23(int n, int e, int nb) {
    __shared__ int sb[MAX_NB];
    int t = threadIdx.x;
    int b = blockIdx.x;
    if (t < MAX_NB) sb[t] = (t < nb) ? g_bsum[t] : 0;
    __syncthreads();
    if (t == 0) {   // serial exclusive prefix over <=49 entries: trivial
        int acc = 0;
        for (int i = 0; i < nb; i++) { int v = sb[i]; sb[i] = acc; acc += v; }
    }
    __syncthreads();
    int boff = sb[b];
    int i = b * SCAN_BS + t;
    if (i < n) {
        int c = g_cnt[i];
        int excl = g_tmp[i] - c + boff;
        g_rowstart[i] = excl;
        g_cursor[i] = excl;
        g_dinv[i] = rsqrtf((float)c + 1.0f);
        if (i == 0) g_rowstart[n] = e;
    }
}

// ------------------------------------------------------------ CSR fill ------
__global__ void k_fill(const int* __restrict__ src, const int* __restrict__ dst, int e) {
    int i = blockIdx.x * blockDim.x + threadIdx.x;
    if (i >= e) return;
    int s = src[i], d = dst[i];
    int pos = atomicAdd(&g_cursor[d], 1);
    int2 pr;
    pr.x = s;
    pr.y = __float_as_int(g_dinv[s] * g_dinv[d]);
    g_edge[pos] = pr;
}

// --------------------------- h = x @ W_conv via mma.sync tf32 ---------------
#define ASTR 132
#define BSTR 136
#define GEMM_SMEM ((128 * ASTR + 128 * BSTR) * 4)

__global__ void __launch_bounds__(256, 1)
k_gemm_mma(const float* __restrict__ x, const float* __restrict__ W, int n) {
    extern __shared__ float sm[];
    float* As = sm;                 // [128][ASTR]
    float* Bs = sm + 128 * ASTR;    // [128][BSTR]
    int t = threadIdx.x;
    int w = t >> 5, lane = t & 31;
    int m0 = blockIdx.x * 128;

    for (int i = t; i < 128 * 32; i += 256) {
        int r = i >> 5, cs = i & 31;
        float4 v = make_float4(0.f, 0.f, 0.f, 0.f);
        if (m0 + r < n) v = ((const float4*)(x + (size_t)(m0 + r) * CC))[cs];
        float4 tv;
        tv.x = __uint_as_float(f2tf32(v.x));
        tv.y = __uint_as_float(f2tf32(v.y));
        tv.z = __uint_as_float(f2tf32(v.z));
        tv.w = __uint_as_float(f2tf32(v.w));
        *(float4*)(As + r * ASTR + cs * 4) = tv;
    }
    for (int i = t; i < 128 * 32; i += 256) {
        int r = i >> 5, cs = i & 31;
        float4 v = ((const float4*)(W + (size_t)r * CC))[cs];
        float4 tv;
        tv.x = __uint_as_float(f2tf32(v.x));
        tv.y = __uint_as_float(f2tf32(v.y));
        tv.z = __uint_as_float(f2tf32(v.z));
        tv.w = __uint_as_float(f2tf32(v.w));
        *(float4*)(Bs + r * BSTR + cs * 4) = tv;
    }
    __syncthreads();

    int wm = (w & 3) * 32;
    int wn = (w >> 2) * 64;
    int grp = lane >> 2;
    int qd  = lane & 3;

    float c[2][8][4];
#pragma unroll
    for (int mi = 0; mi < 2; mi++)
#pragma unroll
        for (int ni = 0; ni < 8; ni++)
#pragma unroll
            for (int q = 0; q < 4; q++) c[mi][ni][q] = 0.f;

#pragma unroll
    for (int k0 = 0; k0 < 128; k0 += 8) {
        uint32_t a[2][4];
#pragma unroll
        for (int mi = 0; mi < 2; mi++) {
            int r0 = wm + mi * 16 + grp;
            a[mi][0] = __float_as_uint(As[r0 * ASTR + k0 + qd]);
            a[mi][1] = __float_as_uint(As[(r0 + 8) * ASTR + k0 + qd]);
            a[mi][2] = __float_as_uint(As[r0 * ASTR + k0 + qd + 4]);
            a[mi][3] = __float_as_uint(As[(r0 + 8) * ASTR + k0 + qd + 4]);
        }
        uint32_t b[8][2];
#pragma unroll
        for (int ni = 0; ni < 8; ni++) {
            int nc = wn + ni * 8 + grp;
            b[ni][0] = __float_as_uint(Bs[(k0 + qd) * BSTR + nc]);
            b[ni][1] = __float_as_uint(Bs[(k0 + qd + 4) * BSTR + nc]);
        }
#pragma unroll
        for (int mi = 0; mi < 2; mi++)
#pragma unroll
            for (int ni = 0; ni < 8; ni++) {
                asm volatile(
                    "mma.sync.aligned.m16n8k8.row.col.f32.tf32.tf32.f32 "
                    "{%0,%1,%2,%3}, {%4,%5,%6,%7}, {%8,%9}, {%0,%1,%2,%3};"
                    : "+f"(c[mi][ni][0]), "+f"(c[mi][ni][1]),
                      "+f"(c[mi][ni][2]), "+f"(c[mi][ni][3])
                    : "r"(a[mi][0]), "r"(a[mi][1]), "r"(a[mi][2]), "r"(a[mi][3]),
                      "r"(b[ni][0]), "r"(b[ni][1]));
            }
    }

#pragma unroll
    for (int mi = 0; mi < 2; mi++) {
        int r0 = m0 + wm + mi * 16 + grp;
#pragma unroll
        for (int ni = 0; ni < 8; ni++) {
            int col = wn + ni * 8 + 2 * qd;
            if (r0 < n)
                *(float2*)(g_h + (size_t)r0 * CC + col) =
                    make_float2(c[mi][ni][0], c[mi][ni][1]);
            if (r0 + 8 < n)
                *(float2*)(g_h + (size_t)(r0 + 8) * CC + col) =
                    make_float2(c[mi][ni][2], c[mi][ni][3]);
        }
    }
}

// ------------- fused: CSR aggregate + relu*x + LN + residual + fc ----------
__global__ void k_aggfin(const float* __restrict__ x,
                         const float* __restrict__ bconv,
                         const float* __restrict__ gamma,
                         const float* __restrict__ beta,
                         const float* __restrict__ Wfc,
                         const float* __restrict__ bfc,
                         float* __restrict__ out, int n) {
    __shared__ float Wfs[CC * KK];
    __shared__ float bcs[CC], gs[CC], bs[CC], bfs[KK];
    __shared__ float ybuf[8][CC];

    int t = threadIdx.x;
    for (int i = t; i < CC * KK; i += 256) Wfs[i] = Wfc[i];
    if (t < CC) { bcs[t] = bconv[t]; gs[t] = gamma[t]; bs[t] = beta[t]; }
    if (t < KK) bfs[t] = bfc[t];
    __syncthreads();

    int wid = t >> 5;
    int lane = t & 31;
    int node = blockIdx.x * 8 + wid;
    if (node >= n) return;

    int rs = g_rowstart[node];
    int re = g_rowstart[node + 1];
    float dsq = g_dinv[node];
    dsq *= dsq;

    float4 acc = ((const float4*)(g_h + (size_t)node * CC))[lane];
    acc.x *= dsq; acc.y *= dsq; acc.z *= dsq; acc.w *= dsq;

    for (int base = rs; base < re; base += 32) {
        int idx = base + lane;
        int s = 0; float nm = 0.f;
        if (idx < re) {
            int2 pr = g_edge[idx];
            s = pr.x;
            nm = __int_as_float(pr.y);
        }
        int m = min(32, re - base);
        int j = 0;
        for (; j + 8 <= m; j += 8) {
            int ss[8]; float nn[8]; float4 vv[8];
#pragma unroll
            for (int q = 0; q < 8; q++) {
                ss[q] = __shfl_sync(0xffffffffu, s, j + q);
                nn[q] = __shfl_sync(0xffffffffu, nm, j + q);
            }
#pragma unroll
            for (int q = 0; q < 8; q++)
                vv[q] = ((const float4*)(g_h + (size_t)ss[q] * CC))[lane];
#pragma unroll
            for (int q = 0; q < 8; q++) {
                acc.x = fmaf(nn[q], vv[q].x, acc.x);
                acc.y = fmaf(nn[q], vv[q].y, acc.y);
                acc.z = fmaf(nn[q], vv[q].z, acc.z);
                acc.w = fmaf(nn[q], vv[q].w, acc.w);
            }
        }
        for (; j + 4 <= m; j += 4) {
            int ss[4]; float nn[4]; float4 vv[4];
#pragma unroll
            for (int q = 0; q < 4; q++) {
                ss[q] = __shfl_sync(0xffffffffu, s, j + q);
                nn[q] = __shfl_sync(0xffffffffu, nm, j + q);
            }
#pragma unroll
            for (int q = 0; q < 4; q++)
                vv[q] = ((const float4*)(g_h + (size_t)ss[q] * CC))[lane];
#pragma unroll
            for (int q = 0; q < 4; q++) {
                acc.x = fmaf(nn[q], vv[q].x, acc.x);
                acc.y = fmaf(nn[q], vv[q].y, acc.y);
                acc.z = fmaf(nn[q], vv[q].z, acc.z);
                acc.w = fmaf(nn[q], vv[q].w, acc.w);
            }
        }
        for (; j < m; j++) {
            int sj = __shfl_sync(0xffffffffu, s, j);
            float nj = __shfl_sync(0xffffffffu, nm, j);
            float4 v = ((const float4*)(g_h + (size_t)sj * CC))[lane];
            acc.x = fmaf(nj, v.x, acc.x); acc.y = fmaf(nj, v.y, acc.y);
            acc.z = fmaf(nj, v.z, acc.z); acc.w = fmaf(nj, v.w, acc.w);
        }
    }

    float4 xv = ((const float4*)(x + (size_t)node * CC))[lane];
    float4 bc = ((const float4*)bcs)[lane];
    acc.x = fmaxf(acc.x + bc.x, 0.f) * xv.x;
    acc.y = fmaxf(acc.y + bc.y, 0.f) * xv.y;
    acc.z = fmaxf(acc.z + bc.z, 0.f) * xv.z;
    acc.w = fmaxf(acc.w + bc.w, 0.f) * xv.w;

    float sU = acc.x + acc.y + acc.z + acc.w;
    float qU = acc.x * acc.x + acc.y * acc.y + acc.z * acc.z + acc.w * acc.w;
#pragma unroll
    for (int off = 16; off >= 1; off >>= 1) {
        sU += __shfl_xor_sync(0xffffffffu, sU, off);
        qU += __shfl_xor_sync(0xffffffffu, qU, off);
    }
    float mu = sU * (1.0f / CC);
    float var = qU * (1.0f / CC) - mu * mu;
    float rstd = rsqrtf(var + LN_EPS);

    float4 g = ((const float4*)gs)[lane];
    float4 b = ((const float4*)bs)[lane];
    float4 y;
    y.x = (acc.x - mu) * rstd * g.x + b.x + xv.x;
    y.y = (acc.y - mu) * rstd * g.y + b.y + xv.y;
    y.z = (acc.z - mu) * rstd * g.z + b.z + xv.z;
    y.w = (acc.w - mu) * rstd * g.w + b.w + xv.w;
    ((float4*)ybuf[wid])[lane] = y;
    __syncwarp();

    for (int k = lane; k < KK; k += 32) {
        float a2 = bfs[k];
#pragma unroll 8
        for (int c = 0; c < CC; c++)
            a2 = fmaf(ybuf[wid][c], Wfs[c * KK + k], a2);
        out[(size_t)node * KK + k] = a2;
    }
}

// ---------------------------------------------------------------- launch ----
extern "C" void kernel_launch(void* const* d_in, const int* in_sizes, int n_in,
                              void* d_out, int out_size) {
    const float* x  = (const float*)d_in[0];
    const int*   ei = (const int*)d_in[1];
    const float* Wc = (const float*)d_in[2];
    const float* bc = (const float*)d_in[3];
    const float* gm = (const float*)d_in[4];
    const float* bt = (const float*)d_in[5];
    const float* Wf = (const float*)d_in[6];
    const float* bf = (const float*)d_in[7];
    float* out = (float*)d_out;

    int n = in_sizes[0] / CC;
    int e = in_sizes[1] / 2;
    const int* src = ei;
    const int* dst = ei + e;
    int nb = (n + SCAN_BS - 1) / SCAN_BS;

    // one-time host-side resources (no device memory)
    static cudaStream_t s2 = nullptr;
    static cudaEvent_t ev_fork = nullptr, ev_gemm = nullptr;
    static void* cnt_ptr = nullptr;
    if (s2 == nullptr) {
        cudaStreamCreateWithFlags(&s2, cudaStreamNonBlocking);
        cudaEventCreateWithFlags(&ev_fork, cudaEventDisableTiming);
        cudaEventCreateWithFlags(&ev_gemm, cudaEventDisableTiming);
        cudaGetSymbolAddress(&cnt_ptr, g_cnt);
        cudaFuncSetAttribute(k_gemm_mma, cudaFuncAttributeMaxDynamicSharedMemorySize,
                             GEMM_SMEM);
    }

    // fork: GEMM on s2, concurrent with CSR build on stream 0
    cudaEventRecord(ev_fork, 0);
    cudaStreamWaitEvent(s2, ev_fork, 0);
    k_gemm_mma<<<(n + 127) / 128, 256, GEMM_SMEM, s2>>>(x, Wc, n);
    cudaEventRecord(ev_gemm, s2);

    // CSR build chain (stream 0)
    cudaMemsetAsync(cnt_ptr, 0, (size_t)n * sizeof(int), 0);
    k_count<<<(e + 255) / 256, 256>>>(dst, e);
    k_scan1<<<nb, SCAN_BS>>>(n);
    k_scan23<<<nb, SCAN_BS>>>(n, e, nb);
    k_fill<<<(e + 255) / 256, 256>>>(src, dst, e);

    // join: aggfin needs both g_h and CSR
    cudaStreamWaitEvent(0, ev_gemm, 0);
    k_aggfin<<<(n + 7) / 8, 256>>>(x, bc, gm, bt, Wf, bf, out, n);
}

// round 11
// speedup vs baseline: 1.4357x; 1.4357x over previous
#include <cuda_runtime.h>
#include <cuda_bf16.h>
#include <cstdint>

#define NN 50000
#define CC 128
#define EE 640000
#define KK 40
#define LN_EPS 1e-5f
#define SCAN_BS 1024
#define MAX_NB 64

// Scratch
__device__ int   g_cnt[NN];
__device__ int   g_rowstart[NN + 1];
__device__ int   g_cursor[NN];
__device__ int   g_tmp[NN];
__device__ int   g_bsum[MAX_NB];
__device__ float g_dinv[NN];
__device__ float g_h[(size_t)NN * CC];
__device__ int2  g_edge[EE];   // (src, norm bits) packed

__device__ __forceinline__ uint32_t f2tf32(float f) {
    uint32_t r;
    asm("cvt.rna.tf32.f32 %0, %1;" : "=r"(r) : "f"(f));
    return r;
}

// ---------------------------------------------------------------- degree ----
__global__ void k_count(const int* __restrict__ dst, int e) {
    int i = blockIdx.x * blockDim.x + threadIdx.x;
    if (i < e) atomicAdd(&g_cnt[dst[i]], 1);
}

// ------------------------------------------------------------------ scan ----
__global__ void k_scan1(int n) {
    __shared__ int sm[SCAN_BS];
    int i = blockIdx.x * SCAN_BS + threadIdx.x;
    int v = (i < n) ? g_cnt[i] : 0;
    sm[threadIdx.x] = v;
    __syncthreads();
#pragma unroll
    for (int off = 1; off < SCAN_BS; off <<= 1) {
        int t = (threadIdx.x >= off) ? sm[threadIdx.x - off] : 0;
        __syncthreads();
        sm[threadIdx.x] += t;
        __syncthreads();
    }
    if (i < n) g_tmp[i] = sm[threadIdx.x];
    if (threadIdx.x == SCAN_BS - 1) g_bsum[blockIdx.x] = sm[SCAN_BS - 1];
}

// scan of block sums fused with final CSR offset/dinv computation
__global__ void k_scan23(int n, int e, int nb) {
    __shared__ int sb[MAX_NB];
    int t = threadIdx.x;
    int b = blockIdx.x;
    if (t < MAX_NB) sb[t] = (t < nb) ? g_bsum[t] : 0;
    __syncthreads();
    if (t == 0) {   // serial exclusive prefix over <=49 entries
        int acc = 0;
        for (int i = 0; i < nb; i++) { int v = sb[i]; sb[i] = acc; acc += v; }
    }
    __syncthreads();
    int boff = sb[b];
    int i = b * SCAN_BS + t;
    if (i < n) {
        int c = g_cnt[i];
        int excl = g_tmp[i] - c + boff;
        g_rowstart[i] = excl;
        g_cursor[i] = excl;
        g_dinv[i] = rsqrtf((float)c + 1.0f);
        if (i == 0) g_rowstart[n] = e;
    }
}

// ------------------------------------------------------------ CSR fill ------
__global__ void k_fill(const int* __restrict__ src, const int* __restrict__ dst, int e) {
    int i = blockIdx.x * blockDim.x + threadIdx.x;
    if (i >= e) return;
    int s = src[i], d = dst[i];
    int pos = atomicAdd(&g_cursor[d], 1);
    int2 pr;
    pr.x = s;
    pr.y = __float_as_int(g_dinv[s] * g_dinv[d]);
    g_edge[pos] = pr;
}

// --------------------------- h = x @ W_conv via mma.sync tf32 ---------------
#define ASTR 132
#define BSTR 136
#define GEMM_SMEM ((128 * ASTR + 128 * BSTR) * 4)

__global__ void __launch_bounds__(256, 1)
k_gemm_mma(const float* __restrict__ x, const float* __restrict__ W, int n) {
    extern __shared__ float sm[];
    float* As = sm;                 // [128][ASTR]
    float* Bs = sm + 128 * ASTR;    // [128][BSTR]
    int t = threadIdx.x;
    int w = t >> 5, lane = t & 31;
    int m0 = blockIdx.x * 128;

    for (int i = t; i < 128 * 32; i += 256) {
        int r = i >> 5, cs = i & 31;
        float4 v = make_float4(0.f, 0.f, 0.f, 0.f);
        if (m0 + r < n) v = ((const float4*)(x + (size_t)(m0 + r) * CC))[cs];
        float4 tv;
        tv.x = __uint_as_float(f2tf32(v.x));
        tv.y = __uint_as_float(f2tf32(v.y));
        tv.z = __uint_as_float(f2tf32(v.z));
        tv.w = __uint_as_float(f2tf32(v.w));
        *(float4*)(As + r * ASTR + cs * 4) = tv;
    }
    for (int i = t; i < 128 * 32; i += 256) {
        int r = i >> 5, cs = i & 31;
        float4 v = ((const float4*)(W + (size_t)r * CC))[cs];
        float4 tv;
        tv.x = __uint_as_float(f2tf32(v.x));
        tv.y = __uint_as_float(f2tf32(v.y));
        tv.z = __uint_as_float(f2tf32(v.z));
        tv.w = __uint_as_float(f2tf32(v.w));
        *(float4*)(Bs + r * BSTR + cs * 4) = tv;
    }
    __syncthreads();

    int wm = (w & 3) * 32;
    int wn = (w >> 2) * 64;
    int grp = lane >> 2;
    int qd  = lane & 3;

    float c[2][8][4];
#pragma unroll
    for (int mi = 0; mi < 2; mi++)
#pragma unroll
        for (int ni = 0; ni < 8; ni++)
#pragma unroll
            for (int q = 0; q < 4; q++) c[mi][ni][q] = 0.f;

#pragma unroll
    for (int k0 = 0; k0 < 128; k0 += 8) {
        uint32_t a[2][4];
#pragma unroll
        for (int mi = 0; mi < 2; mi++) {
            int r0 = wm + mi * 16 + grp;
            a[mi][0] = __float_as_uint(As[r0 * ASTR + k0 + qd]);
            a[mi][1] = __float_as_uint(As[(r0 + 8) * ASTR + k0 + qd]);
            a[mi][2] = __float_as_uint(As[r0 * ASTR + k0 + qd + 4]);
            a[mi][3] = __float_as_uint(As[(r0 + 8) * ASTR + k0 + qd + 4]);
        }
        uint32_t b[8][2];
#pragma unroll
        for (int ni = 0; ni < 8; ni++) {
            int nc = wn + ni * 8 + grp;
            b[ni][0] = __float_as_uint(Bs[(k0 + qd) * BSTR + nc]);
            b[ni][1] = __float_as_uint(Bs[(k0 + qd + 4) * BSTR + nc]);
        }
#pragma unroll
        for (int mi = 0; mi < 2; mi++)
#pragma unroll
            for (int ni = 0; ni < 8; ni++) {
                asm volatile(
                    "mma.sync.aligned.m16n8k8.row.col.f32.tf32.tf32.f32 "
                    "{%0,%1,%2,%3}, {%4,%5,%6,%7}, {%8,%9}, {%0,%1,%2,%3};"
                    : "+f"(c[mi][ni][0]), "+f"(c[mi][ni][1]),
                      "+f"(c[mi][ni][2]), "+f"(c[mi][ni][3])
                    : "r"(a[mi][0]), "r"(a[mi][1]), "r"(a[mi][2]), "r"(a[mi][3]),
                      "r"(b[ni][0]), "r"(b[ni][1]));
            }
    }

#pragma unroll
    for (int mi = 0; mi < 2; mi++) {
        int r0 = m0 + wm + mi * 16 + grp;
#pragma unroll
        for (int ni = 0; ni < 8; ni++) {
            int col = wn + ni * 8 + 2 * qd;
            if (r0 < n)
                *(float2*)(g_h + (size_t)r0 * CC + col) =
                    make_float2(c[mi][ni][0], c[mi][ni][1]);
            if (r0 + 8 < n)
                *(float2*)(g_h + (size_t)(r0 + 8) * CC + col) =
                    make_float2(c[mi][ni][2], c[mi][ni][3]);
        }
    }
}

// ------------- fused: CSR aggregate + relu*x + LN + residual + fc ----------
__global__ void k_aggfin(const float* __restrict__ x,
                         const float* __restrict__ bconv,
                         const float* __restrict__ gamma,
                         const float* __restrict__ beta,
                         const float* __restrict__ Wfc,
                         const float* __restrict__ bfc,
                         float* __restrict__ out, int n) {
    __shared__ float Wfs[CC * KK];
    __shared__ float bcs[CC], gs[CC], bs[CC], bfs[KK];
    __shared__ float ybuf[8][CC];

    int t = threadIdx.x;
    for (int i = t; i < CC * KK; i += 256) Wfs[i] = Wfc[i];
    if (t < CC) { bcs[t] = bconv[t]; gs[t] = gamma[t]; bs[t] = beta[t]; }
    if (t < KK) bfs[t] = bfc[t];
    __syncthreads();

    int wid = t >> 5;
    int lane = t & 31;
    int node = blockIdx.x * 8 + wid;
    if (node >= n) return;

    int rs = g_rowstart[node];
    int re = g_rowstart[node + 1];
    float dsq = g_dinv[node];
    dsq *= dsq;

    float4 acc = ((const float4*)(g_h + (size_t)node * CC))[lane];
    acc.x *= dsq; acc.y *= dsq; acc.z *= dsq; acc.w *= dsq;

    for (int base = rs; base < re; base += 32) {
        int idx = base + lane;
        int s = 0; float nm = 0.f;
        if (idx < re) {
            int2 pr = g_edge[idx];
            s = pr.x;
            nm = __int_as_float(pr.y);
        }
        int m = min(32, re - base);
        int j = 0;
        for (; j + 8 <= m; j += 8) {
            int ss[8]; float nn[8]; float4 vv[8];
#pragma unroll
            for (int q = 0; q < 8; q++) {
                ss[q] = __shfl_sync(0xffffffffu, s, j + q);
                nn[q] = __shfl_sync(0xffffffffu, nm, j + q);
            }
#pragma unroll
            for (int q = 0; q < 8; q++)
                vv[q] = ((const float4*)(g_h + (size_t)ss[q] * CC))[lane];
#pragma unroll
            for (int q = 0; q < 8; q++) {
                acc.x = fmaf(nn[q], vv[q].x, acc.x);
                acc.y = fmaf(nn[q], vv[q].y, acc.y);
                acc.z = fmaf(nn[q], vv[q].z, acc.z);
                acc.w = fmaf(nn[q], vv[q].w, acc.w);
            }
        }
        for (; j + 4 <= m; j += 4) {
            int ss[4]; float nn[4]; float4 vv[4];
#pragma unroll
            for (int q = 0; q < 4; q++) {
                ss[q] = __shfl_sync(0xffffffffu, s, j + q);
                nn[q] = __shfl_sync(0xffffffffu, nm, j + q);
            }
#pragma unroll
            for (int q = 0; q < 4; q++)
                vv[q] = ((const float4*)(g_h + (size_t)ss[q] * CC))[lane];
#pragma unroll
            for (int q = 0; q < 4; q++) {
                acc.x = fmaf(nn[q], vv[q].x, acc.x);
                acc.y = fmaf(nn[q], vv[q].y, acc.y);
                acc.z = fmaf(nn[q], vv[q].z, acc.z);
                acc.w = fmaf(nn[q], vv[q].w, acc.w);
            }
        }
        for (; j < m; j++) {
            int sj = __shfl_sync(0xffffffffu, s, j);
            float nj = __shfl_sync(0xffffffffu, nm, j);
            float4 v = ((const float4*)(g_h + (size_t)sj * CC))[lane];
            acc.x = fmaf(nj, v.x, acc.x); acc.y = fmaf(nj, v.y, acc.y);
            acc.z = fmaf(nj, v.z, acc.z); acc.w = fmaf(nj, v.w, acc.w);
        }
    }

    float4 xv = ((const float4*)(x + (size_t)node * CC))[lane];
    float4 bc = ((const float4*)bcs)[lane];
    acc.x = fmaxf(acc.x + bc.x, 0.f) * xv.x;
    acc.y = fmaxf(acc.y + bc.y, 0.f) * xv.y;
    acc.z = fmaxf(acc.z + bc.z, 0.f) * xv.z;
    acc.w = fmaxf(acc.w + bc.w, 0.f) * xv.w;

    float sU = acc.x + acc.y + acc.z + acc.w;
    float qU = acc.x * acc.x + acc.y * acc.y + acc.z * acc.z + acc.w * acc.w;
#pragma unroll
    for (int off = 16; off >= 1; off >>= 1) {
        sU += __shfl_xor_sync(0xffffffffu, sU, off);
        qU += __shfl_xor_sync(0xffffffffu, qU, off);
    }
    float mu = sU * (1.0f / CC);
    float var = qU * (1.0f / CC) - mu * mu;
    float rstd = rsqrtf(var + LN_EPS);

    float4 g = ((const float4*)gs)[lane];
    float4 b = ((const float4*)bs)[lane];
    float4 y;
    y.x = (acc.x - mu) * rstd * g.x + b.x + xv.x;
    y.y = (acc.y - mu) * rstd * g.y + b.y + xv.y;
    y.z = (acc.z - mu) * rstd * g.z + b.z + xv.z;
    y.w = (acc.w - mu) * rstd * g.w + b.w + xv.w;
    ((float4*)ybuf[wid])[lane] = y;
    __syncwarp();

    for (int k = lane; k < KK; k += 32) {
        float a2 = bfs[k];
#pragma unroll 8
        for (int c = 0; c < CC; c++)
            a2 = fmaf(ybuf[wid][c], Wfs[c * KK + k], a2);
        out[(size_t)node * KK + k] = a2;
    }
}

// ---------------------------------------------------------------- launch ----
extern "C" void kernel_launch(void* const* d_in, const int* in_sizes, int n_in,
                              void* d_out, int out_size) {
    const float* x  = (const float*)d_in[0];
    const int*   ei = (const int*)d_in[1];
    const float* bc = (const float*)d_in[3];
    const float* Wc = (const float*)d_in[2];
    const float* gm = (const float*)d_in[4];
    const float* bt = (const float*)d_in[5];
    const float* Wf = (const float*)d_in[6];
    const float* bf = (const float*)d_in[7];
    float* out = (float*)d_out;

    int n = in_sizes[0] / CC;
    int e = in_sizes[1] / 2;
    const int* src = ei;
    const int* dst = ei + e;
    int nb = (n + SCAN_BS - 1) / SCAN_BS;

    static void* cnt_ptr = nullptr;
    if (cnt_ptr == nullptr) {
        cudaGetSymbolAddress(&cnt_ptr, g_cnt);
        cudaFuncSetAttribute(k_gemm_mma, cudaFuncAttributeMaxDynamicSharedMemorySize,
                             GEMM_SMEM);
    }

    // single-stream pipeline (fork/join regressed in R9/R10 — reverted)
    cudaMemsetAsync(cnt_ptr, 0, (size_t)n * sizeof(int), 0);
    k_count<<<(e + 255) / 256, 256>>>(dst, e);
    k_scan1<<<nb, SCAN_BS>>>(n);
    k_scan23<<<nb, SCAN_BS>>>(n, e, nb);
    k_fill<<<(e + 255) / 256, 256>>>(src, dst, e);

    k_gemm_mma<<<(n + 127) / 128, 256, GEMM_SMEM>>>(x, Wc, n);

    k_aggfin<<<(n + 7) / 8, 256>>>(x, bc, gm, bt, Wf, bf, out, n);
}